// round 6
// baseline (speedup 1.0000x reference)
#include <cuda_runtime.h>
#include <math.h>
#include <math_constants.h>

// Problem dims
#define Bz  128
#define Nf  196
#define Ez  2048
#define Dz  512
#define Az  512
#define Mz  (Bz*Nf)   // 25088

// GEMM tiling
#define MT 64
#define CT 256
#define EK 32

// Scratch (device globals; no allocation allowed)
__device__ float g_att2[Bz*Az];
__device__ float g_scores[Mz];

// ---------------------------------------------------------------------------
// Kernel 1: att2[b,a] = dec[b,:] @ Wd[:,a] + bd[a]; also zero g_scores
// ---------------------------------------------------------------------------
__global__ void k_att2(const float* __restrict__ dec,
                       const float* __restrict__ Wd,
                       const float* __restrict__ bd) {
    __shared__ float dec_s[Dz];
    int b = blockIdx.x, tid = threadIdx.x;
    dec_s[tid]       = dec[b*Dz + tid];
    dec_s[tid + 256] = dec[b*Dz + tid + 256];
    __syncthreads();
    for (int a0 = tid; a0 < Az; a0 += 256) {
        float acc = bd[a0];
        #pragma unroll 8
        for (int d = 0; d < Dz; d++) acc += dec_s[d] * Wd[d*Az + a0];
        g_att2[b*Az + a0] = acc;
    }
    for (int k = blockIdx.x*256 + tid; k < Mz; k += gridDim.x*256)
        g_scores[k] = 0.f;
}

// ---------------------------------------------------------------------------
// Kernel 2: fused scores[m] = sum_c Wf[c]*tanh(enc[m,:]@We[:,c] + be[c] + att2[b,c])
// Tile: MT=64 rows x CT=256 cols per block; grid.y=2 halves of A, atomic reduce.
// ---------------------------------------------------------------------------
__global__ __launch_bounds__(256, 2)
void k_att_gemm(const float* __restrict__ enc,
                const float* __restrict__ We,
                const float* __restrict__ be,
                const float* __restrict__ Wf) {
    __shared__ float We_s[EK][CT];
    __shared__ float enc_s[EK][MT + 1];   // +1 pad: conflict-free transposed store
    __shared__ float red[MT];

    const int tid = threadIdx.x;
    const int tx  = tid & 31;   // column group (strided cols: c = c0 + tx + 32*j)
    const int ty  = tid >> 5;   // row group (rows ty*8 .. ty*8+7)
    const int m0  = blockIdx.x * MT;
    const int c0  = blockIdx.y * CT;

    float acc[8][8];
    #pragma unroll
    for (int i = 0; i < 8; i++)
        #pragma unroll
        for (int j = 0; j < 8; j++) acc[i][j] = 0.f;

    for (int e0 = 0; e0 < Ez; e0 += EK) {
        // Load We tile [EK x CT]: 8192 floats, 8 x float4 per thread, coalesced
        #pragma unroll
        for (int i = 0; i < 8; i++) {
            int lin = i*1024 + tid*4;
            int ek  = lin >> 8;      // /256
            int cc  = lin & 255;
            *(float4*)&We_s[ek][cc] =
                *(const float4*)&We[(size_t)(e0+ek)*Az + c0 + cc];
        }
        // Load enc tile transposed [EK x MT]: coalesced along e, padded store
        #pragma unroll
        for (int i = 0; i < 8; i++) {
            int r  = i*8 + ty;
            int ek = tx;
            enc_s[ek][r] = enc[(size_t)(m0 + r)*Ez + e0 + ek];
        }
        __syncthreads();

        #pragma unroll 4
        for (int ek = 0; ek < EK; ek++) {
            float ev[8], wv[8];
            #pragma unroll
            for (int i = 0; i < 8; i++) ev[i] = enc_s[ek][ty*8 + i];   // broadcast
            #pragma unroll
            for (int j = 0; j < 8; j++) wv[j] = We_s[ek][tx + 32*j];   // conflict-free
            #pragma unroll
            for (int i = 0; i < 8; i++)
                #pragma unroll
                for (int j = 0; j < 8; j++)
                    acc[i][j] += ev[i] * wv[j];
        }
        __syncthreads();
    }

    // Epilogue: + be + att2[b], tanh, dot with Wf, reduce to scores
    float wfv[8], bev[8];
    #pragma unroll
    for (int j = 0; j < 8; j++) {
        int c = c0 + tx + 32*j;
        wfv[j] = Wf[c];
        bev[j] = be[c];
    }
    if (tid < MT) red[tid] = 0.f;
    __syncthreads();

    #pragma unroll
    for (int i = 0; i < 8; i++) {
        int m = m0 + ty*8 + i;
        int b = m / Nf;
        const float* at2 = &g_att2[(size_t)b*Az + c0];
        float p = 0.f;
        #pragma unroll
        for (int j = 0; j < 8; j++) {
            float v = acc[i][j] + bev[j] + at2[tx + 32*j];
            p += wfv[j] * tanhf(v);
        }
        atomicAdd(&red[ty*8 + i], p);
    }
    __syncthreads();
    if (tid < MT) atomicAdd(&g_scores[m0 + tid], red[tid]);
}

// ---------------------------------------------------------------------------
// Kernel 3a: softmax over N per batch; writes alpha into d_out's alpha region
// ---------------------------------------------------------------------------
__global__ void k_softmax(const float* __restrict__ bf,
                          float* __restrict__ alpha_out) {
    const int b = blockIdx.x, tid = threadIdx.x;
    __shared__ float sdata[256];
    float s = (tid < Nf) ? (g_scores[b*Nf + tid] + bf[0]) : -CUDART_INF_F;
    sdata[tid] = s; __syncthreads();
    for (int off = 128; off; off >>= 1) {
        if (tid < off) sdata[tid] = fmaxf(sdata[tid], sdata[tid + off]);
        __syncthreads();
    }
    float mx = sdata[0]; __syncthreads();
    float e = (tid < Nf) ? expf(s - mx) : 0.f;
    sdata[tid] = e; __syncthreads();
    for (int off = 128; off; off >>= 1) {
        if (tid < off) sdata[tid] += sdata[tid + off];
        __syncthreads();
    }
    float inv = 1.f / sdata[0];
    if (tid < Nf) alpha_out[b*Nf + tid] = e * inv;
}

// ---------------------------------------------------------------------------
// Kernel 3b: context[b,e] = sum_n alpha[b,n] * enc[b,n,e]  (HBM-bound re-read)
// ---------------------------------------------------------------------------
__global__ void k_context(const float* __restrict__ enc,
                          const float* __restrict__ alpha,
                          float* __restrict__ ctx) {
    const int b = blockIdx.x;
    const int e = blockIdx.y*256 + threadIdx.x;
    __shared__ float a_s[Nf];
    if (threadIdx.x < Nf) a_s[threadIdx.x] = alpha[b*Nf + threadIdx.x];
    __syncthreads();
    const float* p = enc + (size_t)b*Nf*Ez + e;
    float a0 = 0.f, a1 = 0.f, a2 = 0.f, a3 = 0.f;
    int n = 0;
    for (; n + 4 <= Nf; n += 4) {
        a0 += a_s[n+0] * p[(size_t)(n+0)*Ez];
        a1 += a_s[n+1] * p[(size_t)(n+1)*Ez];
        a2 += a_s[n+2] * p[(size_t)(n+2)*Ez];
        a3 += a_s[n+3] * p[(size_t)(n+3)*Ez];
    }
    for (; n < Nf; n++) a0 += a_s[n] * p[(size_t)n*Ez];
    ctx[(size_t)b*Ez + e] = a0 + a1 + a2 + a3;
}

// ---------------------------------------------------------------------------
// kernel_launch: inputs in metadata order:
// 0 encoder_out [B,N,E], 1 decoder_hidden [B,D], 2 We [E,A], 3 be [A],
// 4 Wd [D,A], 5 bd [A], 6 Wf [A,1], 7 bf [1]
// output: context [B,E] then alpha [B,N,1], concatenated fp32
// ---------------------------------------------------------------------------
extern "C" void kernel_launch(void* const* d_in, const int* in_sizes, int n_in,
                              void* d_out, int out_size) {
    const float* enc = (const float*)d_in[0];
    const float* dec = (const float*)d_in[1];
    const float* We  = (const float*)d_in[2];
    const float* be  = (const float*)d_in[3];
    const float* Wd  = (const float*)d_in[4];
    const float* bd  = (const float*)d_in[5];
    const float* Wf  = (const float*)d_in[6];
    const float* bf  = (const float*)d_in[7];

    float* out   = (float*)d_out;
    float* ctx   = out;                 // [B, E]
    float* alpha = out + (size_t)Bz*Ez; // [B, N]

    k_att2<<<Bz, 256>>>(dec, Wd, bd);
    dim3 g2(Mz/MT, Az/CT);              // (392, 2)
    k_att_gemm<<<g2, 256>>>(enc, We, be, Wf);
    k_softmax<<<Bz, 256>>>(bf, alpha);
    dim3 g3(Bz, Ez/256);                // (128, 8)
    k_context<<<g3, 256>>>(enc, alpha, ctx);
}

// round 8
// speedup vs baseline: 3.1632x; 3.1632x over previous
#include <cuda_runtime.h>
#include <math.h>
#include <math_constants.h>
#include <stdint.h>

// Problem dims
#define Bz  128
#define Nf  196
#define Ez  2048
#define Dz  512
#define Az  512
#define Mz  (Bz*Nf)   // 25088

// GEMM tiling
#define BM  128
#define BN  128
#define TK  32
#define KSTAGES (Ez/TK)   // 64

// SMEM (floats): A[2][128][36], B[2][32][136], red[128]
#define A_STRIDE 36
#define B_STRIDE 136
#define A_STG (BM*A_STRIDE)          // 4608
#define B_STG (TK*B_STRIDE)          // 4352
#define OFF_A 0
#define OFF_B (2*A_STG)              // 9216
#define OFF_RED (OFF_B + 2*B_STG)    // 17920
#define SMEM_FLOATS (OFF_RED + BM)   // 18048
#define SMEM_BYTES (SMEM_FLOATS*4)   // 72192

// Scratch (device globals; no allocation allowed)
__device__ float g_att2[Bz*Az];
__device__ float g_scores[Mz];

// ---------------------------------------------------------------------------
// PTX helpers (all valid for plain sm_103 target: cp.async sm_80+, mma sm_80+)
// ---------------------------------------------------------------------------
__device__ __forceinline__ uint32_t smem_u32(const void* p) {
    uint32_t a;
    asm("{ .reg .u64 t; cvta.to.shared.u64 t, %1; cvt.u32.u64 %0, t; }"
        : "=r"(a) : "l"(p));
    return a;
}

#define CP_ASYNC16(s, g) \
    asm volatile("cp.async.cg.shared.global [%0], [%1], 16;" :: "r"(s), "l"(g))
#define CP_COMMIT() asm volatile("cp.async.commit_group;" ::: "memory")
#define CP_WAIT1()  asm volatile("cp.async.wait_group 1;" ::: "memory")
#define CP_WAIT0()  asm volatile("cp.async.wait_group 0;" ::: "memory")

__device__ __forceinline__ uint32_t f2tf(float x) {
    uint32_t r;
    asm("cvt.rna.tf32.f32 %0, %1;" : "=r"(r) : "f"(x));
    return r;
}

__device__ __forceinline__ void mma_tf32(float* c, const uint32_t* a,
                                         const uint32_t* b) {
    asm volatile(
        "mma.sync.aligned.m16n8k8.row.col.f32.tf32.tf32.f32 "
        "{%0,%1,%2,%3}, {%4,%5,%6,%7}, {%8,%9}, {%0,%1,%2,%3};"
        : "+f"(c[0]), "+f"(c[1]), "+f"(c[2]), "+f"(c[3])
        : "r"(a[0]), "r"(a[1]), "r"(a[2]), "r"(a[3]), "r"(b[0]), "r"(b[1]));
}

// ---------------------------------------------------------------------------
// Kernel 1: att2[b,a] = dec[b,:] @ Wd[:,a] + bd[a]; also zero g_scores
// ---------------------------------------------------------------------------
__global__ void k_att2(const float* __restrict__ dec,
                       const float* __restrict__ Wd,
                       const float* __restrict__ bd) {
    __shared__ float dec_s[Dz];
    int b = blockIdx.x, tid = threadIdx.x;
    dec_s[tid]       = dec[b*Dz + tid];
    dec_s[tid + 256] = dec[b*Dz + tid + 256];
    __syncthreads();
    for (int a0 = tid; a0 < Az; a0 += 256) {
        float acc = bd[a0];
        #pragma unroll 8
        for (int d = 0; d < Dz; d++) acc += dec_s[d] * Wd[d*Az + a0];
        g_att2[b*Az + a0] = acc;
    }
    for (int k = blockIdx.x*256 + tid; k < Mz; k += gridDim.x*256)
        g_scores[k] = 0.f;
}

// ---------------------------------------------------------------------------
// Kernel 2: tf32 mma.sync GEMM + fused tanh/Wf epilogue
// CTA computes att1 tile [128 rows x 128 attention-cols]; partial scores
// reduced in smem then atomically accumulated into g_scores.
// 8 warps: warp_m = wid&1 (64 rows), warp_n = wid>>1 (32 cols).
// ---------------------------------------------------------------------------
__global__ __launch_bounds__(256, 2)
void k_gemm(const float* __restrict__ enc,
            const float* __restrict__ We,
            const float* __restrict__ be,
            const float* __restrict__ Wf) {
    extern __shared__ float sm[];
    const uint32_t sb = smem_u32(sm);
    const int tid  = threadIdx.x;
    const int lane = tid & 31;
    const int gid  = lane >> 2;      // 0..7
    const int tg   = lane & 3;       // 0..3
    const int wm   = (tid >> 5) & 1; // warp_m
    const int wn   = (tid >> 5) >> 1;// warp_n 0..3
    const int n0   = blockIdx.x * BN;   // n fastest -> L2 reuse of enc
    const int m0   = blockIdx.y * BM;

    // async load of one K-stage into buffer st
    auto load_stage = [&](int ks, int st) {
        const int k0 = ks * TK;
        // A tile: 128 rows x 32 k = 1024 16B-chunks, 4 per thread
        #pragma unroll
        for (int i = 0; i < 4; i++) {
            int f   = tid + i*256;
            int row = f >> 3, kq = f & 7;
            uint32_t dst = sb + (OFF_A + st*A_STG + row*A_STRIDE + kq*4)*4;
            CP_ASYNC16(dst, enc + (size_t)(m0 + row)*Ez + k0 + kq*4);
        }
        // B tile: 32 k-rows x 128 n = 1024 chunks, 4 per thread
        #pragma unroll
        for (int i = 0; i < 4; i++) {
            int f   = tid + i*256;
            int row = f >> 5, nq = f & 31;
            uint32_t dst = sb + (OFF_B + st*B_STG + row*B_STRIDE + nq*4)*4;
            CP_ASYNC16(dst, We + (size_t)(k0 + row)*Az + n0 + nq*4);
        }
    };

    float acc[4][4][4];
    #pragma unroll
    for (int mt = 0; mt < 4; mt++)
        #pragma unroll
        for (int nt = 0; nt < 4; nt++)
            #pragma unroll
            for (int q = 0; q < 4; q++) acc[mt][nt][q] = 0.f;

    load_stage(0, 0);
    CP_COMMIT();

    for (int ks = 0; ks < KSTAGES; ks++) {
        const int cur = ks & 1;
        if (ks + 1 < KSTAGES) {
            load_stage(ks + 1, cur ^ 1);
            CP_COMMIT();
            CP_WAIT1();
        } else {
            CP_WAIT0();
        }
        __syncthreads();

        const float* Abuf = sm + OFF_A + cur*A_STG;
        const float* Bbuf = sm + OFF_B + cur*B_STG;
        #pragma unroll
        for (int k8 = 0; k8 < 4; k8++) {
            const int kb = k8 * 8;
            uint32_t af[4][4];
            #pragma unroll
            for (int mt = 0; mt < 4; mt++) {
                const float* Ab = Abuf + (wm*64 + mt*16 + gid)*A_STRIDE + kb + tg;
                af[mt][0] = f2tf(Ab[0]);
                af[mt][1] = f2tf(Ab[8*A_STRIDE]);
                af[mt][2] = f2tf(Ab[4]);
                af[mt][3] = f2tf(Ab[8*A_STRIDE + 4]);
            }
            uint32_t bfr[4][2];
            #pragma unroll
            for (int nt = 0; nt < 4; nt++) {
                const float* Bb = Bbuf + (kb + tg)*B_STRIDE + wn*32 + nt*8 + gid;
                bfr[nt][0] = f2tf(Bb[0]);
                bfr[nt][1] = f2tf(Bb[4*B_STRIDE]);
            }
            #pragma unroll
            for (int mt = 0; mt < 4; mt++)
                #pragma unroll
                for (int nt = 0; nt < 4; nt++)
                    mma_tf32(acc[mt][nt], af[mt], bfr[nt]);
        }
        __syncthreads();
    }

    // Epilogue: v = acc + be[c] + att2[b,c]; p += Wf[c]*tanh(v); reduce rows.
    float* red = sm + OFF_RED;
    if (tid < BM) red[tid] = 0.f;
    __syncthreads();

    #pragma unroll
    for (int mt = 0; mt < 4; mt++) {
        #pragma unroll
        for (int r2 = 0; r2 < 2; r2++) {
            int mloc = wm*64 + mt*16 + r2*8 + gid;
            int m = m0 + mloc;
            int b = m / Nf;
            const float* at2 = g_att2 + (size_t)b*Az;
            float p = 0.f;
            #pragma unroll
            for (int nt = 0; nt < 4; nt++) {
                #pragma unroll
                for (int cc = 0; cc < 2; cc++) {
                    int c = n0 + wn*32 + nt*8 + 2*tg + cc;
                    float v = acc[mt][nt][r2*2 + cc] + be[c] + at2[c];
                    p += Wf[c] * tanhf(v);
                }
            }
            atomicAdd(&red[mloc], p);
        }
    }
    __syncthreads();
    if (tid < BM) atomicAdd(&g_scores[m0 + tid], red[tid]);
}

// ---------------------------------------------------------------------------
// Kernel 3a: softmax over N per batch
// ---------------------------------------------------------------------------
__global__ void k_softmax(const float* __restrict__ bf,
                          float* __restrict__ alpha_out) {
    const int b = blockIdx.x, tid = threadIdx.x;
    __shared__ float sdata[256];
    float s = (tid < Nf) ? (g_scores[b*Nf + tid] + bf[0]) : -CUDART_INF_F;
    sdata[tid] = s; __syncthreads();
    for (int off = 128; off; off >>= 1) {
        if (tid < off) sdata[tid] = fmaxf(sdata[tid], sdata[tid + off]);
        __syncthreads();
    }
    float mx = sdata[0]; __syncthreads();
    float e = (tid < Nf) ? expf(s - mx) : 0.f;
    sdata[tid] = e; __syncthreads();
    for (int off = 128; off; off >>= 1) {
        if (tid < off) sdata[tid] += sdata[tid + off];
        __syncthreads();
    }
    float inv = 1.f / sdata[0];
    if (tid < Nf) alpha_out[b*Nf + tid] = e * inv;
}

// ---------------------------------------------------------------------------
// Kernel 3b: context[b,e] = sum_n alpha[b,n] * enc[b,n,e]  (float4)
// ---------------------------------------------------------------------------
__global__ void k_context(const float* __restrict__ enc,
                          const float* __restrict__ alpha,
                          float* __restrict__ ctx) {
    const int b = blockIdx.x;
    const int e4 = blockIdx.y * 256 + threadIdx.x;   // float4 index, Ez/4=512
    __shared__ float a_s[Nf];
    if (threadIdx.x < Nf) a_s[threadIdx.x] = alpha[b*Nf + threadIdx.x];
    __syncthreads();
    const float4* p = (const float4*)(enc + (size_t)b*Nf*Ez) + e4;
    float4 s0 = {0,0,0,0}, s1 = {0,0,0,0}, s2 = {0,0,0,0}, s3 = {0,0,0,0};
    #pragma unroll 4
    for (int n = 0; n < Nf; n += 4) {   // 196 = 4*49 exact
        float4 v0 = p[(size_t)(n+0)*(Ez/4)];
        float4 v1 = p[(size_t)(n+1)*(Ez/4)];
        float4 v2 = p[(size_t)(n+2)*(Ez/4)];
        float4 v3 = p[(size_t)(n+3)*(Ez/4)];
        float a0 = a_s[n], a1 = a_s[n+1], a2 = a_s[n+2], a3 = a_s[n+3];
        s0.x += a0*v0.x; s0.y += a0*v0.y; s0.z += a0*v0.z; s0.w += a0*v0.w;
        s1.x += a1*v1.x; s1.y += a1*v1.y; s1.z += a1*v1.z; s1.w += a1*v1.w;
        s2.x += a2*v2.x; s2.y += a2*v2.y; s2.z += a2*v2.z; s2.w += a2*v2.w;
        s3.x += a3*v3.x; s3.y += a3*v3.y; s3.z += a3*v3.z; s3.w += a3*v3.w;
    }
    float4 r;
    r.x = (s0.x + s1.x) + (s2.x + s3.x);
    r.y = (s0.y + s1.y) + (s2.y + s3.y);
    r.z = (s0.z + s1.z) + (s2.z + s3.z);
    r.w = (s0.w + s1.w) + (s2.w + s3.w);
    ((float4*)ctx)[(size_t)b*(Ez/4) + e4] = r;
}

// ---------------------------------------------------------------------------
// kernel_launch: inputs in metadata order:
// 0 encoder_out [B,N,E], 1 decoder_hidden [B,D], 2 We [E,A], 3 be [A],
// 4 Wd [D,A], 5 bd [A], 6 Wf [A,1], 7 bf [1]
// output: context [B,E] then alpha [B,N,1], concatenated fp32
// ---------------------------------------------------------------------------
extern "C" void kernel_launch(void* const* d_in, const int* in_sizes, int n_in,
                              void* d_out, int out_size) {
    const float* enc = (const float*)d_in[0];
    const float* dec = (const float*)d_in[1];
    const float* We  = (const float*)d_in[2];
    const float* be  = (const float*)d_in[3];
    const float* Wd  = (const float*)d_in[4];
    const float* bd  = (const float*)d_in[5];
    const float* Wf  = (const float*)d_in[6];
    const float* bf  = (const float*)d_in[7];

    float* out   = (float*)d_out;
    float* ctx   = out;                 // [B, E]
    float* alpha = out + (size_t)Bz*Ez; // [B, N]

    static bool attr_set = false;
    if (!attr_set) {
        cudaFuncSetAttribute(k_gemm, cudaFuncAttributeMaxDynamicSharedMemorySize,
                             SMEM_BYTES);
        attr_set = true;
    }

    k_att2<<<Bz, 256>>>(dec, Wd, bd);
    k_gemm<<<dim3(Az/BN, Mz/BM), 256, SMEM_BYTES>>>(enc, We, be, Wf);
    k_softmax<<<Bz, 256>>>(bf, alpha);
    k_context<<<dim3(Bz, Ez/1024), 256>>>(enc, alpha, ctx);
}

// round 9
// speedup vs baseline: 3.2720x; 1.0344x over previous
#include <cuda_runtime.h>
#include <math.h>
#include <math_constants.h>
#include <stdint.h>

// Problem dims
#define Bz  128
#define Nf  196
#define Ez  2048
#define Dz  512
#define Az  512
#define Mz  (Bz*Nf)   // 25088

// GEMM tiling
#define BM  128
#define BN  128
#define TK  32
#define KSTAGES (Ez/TK)   // 64
#define NSTG 3

// SMEM (floats): A[3][128][36], B[3][32][136], red[128]
#define A_STRIDE 36
#define B_STRIDE 136
#define A_STG (BM*A_STRIDE)          // 4608
#define B_STG (TK*B_STRIDE)          // 4352
#define OFF_A 0
#define OFF_B (NSTG*A_STG)           // 13824
#define OFF_RED (OFF_B + NSTG*B_STG) // 26880
#define SMEM_FLOATS (OFF_RED + BM)   // 27008
#define SMEM_BYTES (SMEM_FLOATS*4)   // 108032

// Scratch (device globals; no allocation allowed)
__device__ float g_att2[Bz*Az];
__device__ float g_scores[Mz];

// ---------------------------------------------------------------------------
// PTX helpers (valid for plain sm_103 target)
// ---------------------------------------------------------------------------
__device__ __forceinline__ uint32_t smem_u32(const void* p) {
    uint32_t a;
    asm("{ .reg .u64 t; cvta.to.shared.u64 t, %1; cvt.u32.u64 %0, t; }"
        : "=r"(a) : "l"(p));
    return a;
}

#define CP_ASYNC16(s, g) \
    asm volatile("cp.async.cg.shared.global [%0], [%1], 16;" :: "r"(s), "l"(g))
#define CP_COMMIT() asm volatile("cp.async.commit_group;" ::: "memory")
#define CP_WAIT(n)  asm volatile("cp.async.wait_group %0;" :: "n"(n) : "memory")

__device__ __forceinline__ void mma_tf32(float* c, const uint32_t* a,
                                         const uint32_t* b) {
    asm volatile(
        "mma.sync.aligned.m16n8k8.row.col.f32.tf32.tf32.f32 "
        "{%0,%1,%2,%3}, {%4,%5,%6,%7}, {%8,%9}, {%0,%1,%2,%3};"
        : "+f"(c[0]), "+f"(c[1]), "+f"(c[2]), "+f"(c[3])
        : "r"(a[0]), "r"(a[1]), "r"(a[2]), "r"(a[3]), "r"(b[0]), "r"(b[1]));
}

// ---------------------------------------------------------------------------
// Kernel 1: att2[b,a] = dec[b,:] @ Wd[:,a] + bd[a]; also zero g_scores
// ---------------------------------------------------------------------------
__global__ void k_att2(const float* __restrict__ dec,
                       const float* __restrict__ Wd,
                       const float* __restrict__ bd) {
    __shared__ float dec_s[Dz];
    int b = blockIdx.x, tid = threadIdx.x;
    dec_s[tid]       = dec[b*Dz + tid];
    dec_s[tid + 256] = dec[b*Dz + tid + 256];
    __syncthreads();
    for (int a0 = tid; a0 < Az; a0 += 256) {
        float acc = bd[a0];
        #pragma unroll 8
        for (int d = 0; d < Dz; d++) acc += dec_s[d] * Wd[d*Az + a0];
        g_att2[b*Az + a0] = acc;
    }
    for (int k = blockIdx.x*256 + tid; k < Mz; k += gridDim.x*256)
        g_scores[k] = 0.f;
}

// ---------------------------------------------------------------------------
// Kernel 2: tf32 mma.sync GEMM + fused tanh/Wf epilogue.
// Raw fp32 bits fed to tf32 MMA (HW truncates low 13 mantissa bits) — no cvt.
// 3-stage cp.async pipeline, wait_group 2.
// ---------------------------------------------------------------------------
__global__ __launch_bounds__(256, 2)
void k_gemm(const float* __restrict__ enc,
            const float* __restrict__ We,
            const float* __restrict__ be,
            const float* __restrict__ Wf) {
    extern __shared__ float sm[];
    const uint32_t sb = smem_u32(sm);
    const int tid  = threadIdx.x;
    const int lane = tid & 31;
    const int gid  = lane >> 2;      // 0..7
    const int tg   = lane & 3;       // 0..3
    const int wm   = (tid >> 5) & 1; // warp_m
    const int wn   = (tid >> 5) >> 1;// warp_n 0..3
    const int n0   = blockIdx.x * BN;   // n fastest -> L2 reuse of enc
    const int m0   = blockIdx.y * BM;

    auto load_stage = [&](int ks, int st) {
        const int k0 = ks * TK;
        #pragma unroll
        for (int i = 0; i < 4; i++) {
            int f   = tid + i*256;
            int row = f >> 3, kq = f & 7;
            uint32_t dst = sb + (OFF_A + st*A_STG + row*A_STRIDE + kq*4)*4;
            CP_ASYNC16(dst, enc + (size_t)(m0 + row)*Ez + k0 + kq*4);
        }
        #pragma unroll
        for (int i = 0; i < 4; i++) {
            int f   = tid + i*256;
            int row = f >> 5, nq = f & 31;
            uint32_t dst = sb + (OFF_B + st*B_STG + row*B_STRIDE + nq*4)*4;
            CP_ASYNC16(dst, We + (size_t)(k0 + row)*Az + n0 + nq*4);
        }
    };

    float acc[4][4][4];
    #pragma unroll
    for (int mt = 0; mt < 4; mt++)
        #pragma unroll
        for (int nt = 0; nt < 4; nt++)
            #pragma unroll
            for (int q = 0; q < 4; q++) acc[mt][nt][q] = 0.f;

    load_stage(0, 0); CP_COMMIT();
    load_stage(1, 1); CP_COMMIT();

    int cur = 0;
    for (int ks = 0; ks < KSTAGES; ks++) {
        if (ks + 2 < KSTAGES) {
            load_stage(ks + 2, (ks + 2) % NSTG);
            CP_COMMIT();
            CP_WAIT(2);
        } else if (ks + 1 < KSTAGES) {
            CP_WAIT(1);
        } else {
            CP_WAIT(0);
        }
        __syncthreads();

        const uint32_t* Abuf = (const uint32_t*)(sm + OFF_A + cur*A_STG);
        const uint32_t* Bbuf = (const uint32_t*)(sm + OFF_B + cur*B_STG);
        #pragma unroll
        for (int k8 = 0; k8 < 4; k8++) {
            const int kb = k8 * 8;
            uint32_t af[4][4];
            #pragma unroll
            for (int mt = 0; mt < 4; mt++) {
                const uint32_t* Ab = Abuf + (wm*64 + mt*16 + gid)*A_STRIDE + kb + tg;
                af[mt][0] = Ab[0];
                af[mt][1] = Ab[8*A_STRIDE];
                af[mt][2] = Ab[4];
                af[mt][3] = Ab[8*A_STRIDE + 4];
            }
            uint32_t bfr[4][2];
            #pragma unroll
            for (int nt = 0; nt < 4; nt++) {
                const uint32_t* Bb = Bbuf + (kb + tg)*B_STRIDE + wn*32 + nt*8 + gid;
                bfr[nt][0] = Bb[0];
                bfr[nt][1] = Bb[4*B_STRIDE];
            }
            #pragma unroll
            for (int mt = 0; mt < 4; mt++)
                #pragma unroll
                for (int nt = 0; nt < 4; nt++)
                    mma_tf32(acc[mt][nt], af[mt], bfr[nt]);
        }
        __syncthreads();   // all reads of 'cur' done before its buffer is refilled
        cur = (cur + 1) % NSTG;
    }

    // Epilogue: v = acc + be[c] + att2[b,c]; p += Wf[c]*tanh(v); reduce rows.
    float* red = sm + OFF_RED;
    if (tid < BM) red[tid] = 0.f;
    __syncthreads();

    #pragma unroll
    for (int mt = 0; mt < 4; mt++) {
        #pragma unroll
        for (int r2 = 0; r2 < 2; r2++) {
            int mloc = wm*64 + mt*16 + r2*8 + gid;
            int m = m0 + mloc;
            int b = m / Nf;
            const float* at2 = g_att2 + (size_t)b*Az;
            float p = 0.f;
            #pragma unroll
            for (int nt = 0; nt < 4; nt++) {
                #pragma unroll
                for (int cc = 0; cc < 2; cc++) {
                    int c = n0 + wn*32 + nt*8 + 2*tg + cc;
                    float v = acc[mt][nt][r2*2 + cc] + be[c] + at2[c];
                    p += Wf[c] * tanhf(v);
                }
            }
            atomicAdd(&red[mloc], p);
        }
    }
    __syncthreads();
    if (tid < BM) atomicAdd(&g_scores[m0 + tid], red[tid]);
}

// ---------------------------------------------------------------------------
// Kernel 3a: softmax over N per batch
// ---------------------------------------------------------------------------
__global__ void k_softmax(const float* __restrict__ bf,
                          float* __restrict__ alpha_out) {
    const int b = blockIdx.x, tid = threadIdx.x;
    __shared__ float sdata[256];
    float s = (tid < Nf) ? (g_scores[b*Nf + tid] + bf[0]) : -CUDART_INF_F;
    sdata[tid] = s; __syncthreads();
    for (int off = 128; off; off >>= 1) {
        if (tid < off) sdata[tid] = fmaxf(sdata[tid], sdata[tid + off]);
        __syncthreads();
    }
    float mx = sdata[0]; __syncthreads();
    float e = (tid < Nf) ? expf(s - mx) : 0.f;
    sdata[tid] = e; __syncthreads();
    for (int off = 128; off; off >>= 1) {
        if (tid < off) sdata[tid] += sdata[tid + off];
        __syncthreads();
    }
    float inv = 1.f / sdata[0];
    if (tid < Nf) alpha_out[b*Nf + tid] = e * inv;
}

// ---------------------------------------------------------------------------
// Kernel 3b: context[b,e] = sum_n alpha[b,n] * enc[b,n,e]
// grid (Bz, 4) x 128 threads, one float4 column per thread -> 512 CTAs.
// ---------------------------------------------------------------------------
__global__ __launch_bounds__(128)
void k_context(const float* __restrict__ enc,
               const float* __restrict__ alpha,
               float* __restrict__ ctx) {
    const int b  = blockIdx.x;
    const int e4 = blockIdx.y * 128 + threadIdx.x;   // 0..511
    __shared__ float a_s[Nf];
    for (int n = threadIdx.x; n < Nf; n += 128) a_s[n] = alpha[b*Nf + n];
    __syncthreads();
    const float4* p = (const float4*)(enc + (size_t)b*Nf*Ez) + e4;
    float4 s0 = {0,0,0,0}, s1 = {0,0,0,0}, s2 = {0,0,0,0}, s3 = {0,0,0,0};
    #pragma unroll 4
    for (int n = 0; n < Nf; n += 4) {   // 196 = 4*49 exact
        float4 v0 = p[(size_t)(n+0)*(Ez/4)];
        float4 v1 = p[(size_t)(n+1)*(Ez/4)];
        float4 v2 = p[(size_t)(n+2)*(Ez/4)];
        float4 v3 = p[(size_t)(n+3)*(Ez/4)];
        float a0 = a_s[n], a1 = a_s[n+1], a2 = a_s[n+2], a3 = a_s[n+3];
        s0.x += a0*v0.x; s0.y += a0*v0.y; s0.z += a0*v0.z; s0.w += a0*v0.w;
        s1.x += a1*v1.x; s1.y += a1*v1.y; s1.z += a1*v1.z; s1.w += a1*v1.w;
        s2.x += a2*v2.x; s2.y += a2*v2.y; s2.z += a2*v2.z; s2.w += a2*v2.w;
        s3.x += a3*v3.x; s3.y += a3*v3.y; s3.z += a3*v3.z; s3.w += a3*v3.w;
    }
    float4 r;
    r.x = (s0.x + s1.x) + (s2.x + s3.x);
    r.y = (s0.y + s1.y) + (s2.y + s3.y);
    r.z = (s0.z + s1.z) + (s2.z + s3.z);
    r.w = (s0.w + s1.w) + (s2.w + s3.w);
    ((float4*)ctx)[(size_t)b*(Ez/4) + e4] = r;
}

// ---------------------------------------------------------------------------
// kernel_launch: inputs in metadata order:
// 0 encoder_out [B,N,E], 1 decoder_hidden [B,D], 2 We [E,A], 3 be [A],
// 4 Wd [D,A], 5 bd [A], 6 Wf [A,1], 7 bf [1]
// output: context [B,E] then alpha [B,N,1], concatenated fp32
// ---------------------------------------------------------------------------
extern "C" void kernel_launch(void* const* d_in, const int* in_sizes, int n_in,
                              void* d_out, int out_size) {
    const float* enc = (const float*)d_in[0];
    const float* dec = (const float*)d_in[1];
    const float* We  = (const float*)d_in[2];
    const float* be  = (const float*)d_in[3];
    const float* Wd  = (const float*)d_in[4];
    const float* bd  = (const float*)d_in[5];
    const float* Wf  = (const float*)d_in[6];
    const float* bf  = (const float*)d_in[7];

    float* out   = (float*)d_out;
    float* ctx   = out;                 // [B, E]
    float* alpha = out + (size_t)Bz*Ez; // [B, N]

    static bool attr_set = false;
    if (!attr_set) {
        cudaFuncSetAttribute(k_gemm, cudaFuncAttributeMaxDynamicSharedMemorySize,
                             SMEM_BYTES);
        attr_set = true;
    }

    k_att2<<<Bz, 256>>>(dec, Wd, bd);
    k_gemm<<<dim3(Az/BN, Mz/BM), 256, SMEM_BYTES>>>(enc, We, be, Wf);
    k_softmax<<<Bz, 256>>>(bf, alpha);
    k_context<<<dim3(Bz, 4), 128>>>(enc, alpha, ctx);
}